// round 9
// baseline (speedup 1.0000x reference)
#include <cuda_runtime.h>
#include <stdint.h>
#include <stddef.h>

#define N_NODES 10000
#define DIM 40
#define KSEL 32
#define ALPHA 3.0f
#define JTILE 64
#define RPB 8                      // rows per block (one warp per row)
#define NGROUPS (N_NODES / RPB)    // 1250 blocks
#define TPAD 65                    // padded tile row stride (bank-conflict-free)

// ---------------- device scratch (no allocation allowed) ----------------
__device__ int g_fail[N_NODES];
__device__ int g_nfail = 0;

// ---------------- XLA EmitFastTanh replica (with-FMA variant) ----------------
__device__ __forceinline__ float xla_tanh(float x) {
    const float kClamp = 7.99881172180175781f;
    float ax = fabsf(x);
    float xc = fminf(fmaxf(x, -kClamp), kClamp);
    float x2 = xc * xc;
    float num = -2.76076847742355e-16f;
    num = fmaf(x2, num,  2.00018790482477e-13f);
    num = fmaf(x2, num, -8.60467152213735e-11f);
    num = fmaf(x2, num,  5.12229709037114e-08f);
    num = fmaf(x2, num,  1.48572235717979e-05f);
    num = fmaf(x2, num,  6.37261928875436e-04f);
    num = fmaf(x2, num,  4.89352455891786e-03f);
    num = xc * num;
    float den = 1.19825839466702e-06f;
    den = fmaf(x2, den, 1.18534705686654e-04f);
    den = fmaf(x2, den, 2.26843463243900e-03f);
    den = fmaf(x2, den, 4.89352518554385e-03f);
    float r = num / den;
    return (ax < 0.0004f) ? x : r;
}

// ---------------- mega: fully independent zero + on-the-fly P/Q + scan ----------------
__global__ void __launch_bounds__(256, 2) mega_kernel(
        const int* __restrict__ idx,
        const float* __restrict__ emb1,
        const float* __restrict__ emb2,
        const float* __restrict__ W1,
        const float* __restrict__ b1,
        const float* __restrict__ W2,
        const float* __restrict__ b2,
        float* __restrict__ out) {
    __shared__ __align__(16) float sW1t[DIM * DIM];     // [k][d]
    __shared__ __align__(16) float sW2t[DIM * DIM];
    __shared__ float sb2[2 * DIM];
    __shared__ __align__(16) float A[DIM * TPAD];       // te1 [j][k] -> tP [d][j] padded
    __shared__ __align__(16) float B[DIM * TPAD];       // te2 [j][k] -> tQ [d][j] padded
    __shared__ __align__(16) float se1[RPB * DIM];
    __shared__ __align__(16) float se2[RPB * DIM];
    __shared__ float sPo[RPB][DIM];
    __shared__ float sQo[RPB][DIM];
    __shared__ int sidx[JTILE];
    __shared__ int s_done;

    const int tid  = threadIdx.x;
    const int lane = tid & 31;
    const int w    = tid >> 5;
    const int row0 = blockIdx.x * RPB;
    const int row  = row0 + w;

    // ---- 1: zero own 8 output rows FIRST (stores flow from t=0) ----
    {
        float4* o4 = reinterpret_cast<float4*>(out + (size_t)row0 * N_NODES);
        const float4 z = make_float4(0.f, 0.f, 0.f, 0.f);
        for (int i = tid; i < RPB * N_NODES / 4; i += 256)
            __stcs(&o4[i], z);
    }

    // ---- 2: stage W (transposed), biases, own embedding rows ----
    for (int e = tid; e < DIM * DIM; e += 256) {
        int d = e / DIM, k = e % DIM;
        sW1t[k * DIM + d] = W1[e];
        sW2t[k * DIM + d] = W2[e];
    }
    if (tid < 2 * DIM)
        sb2[tid] = (tid < DIM) ? b1[tid] : b2[tid - DIM];
    if (tid < RPB * (DIM / 4)) {               // 80 threads: float4 gather of own rows
        int r = tid / (DIM / 4), q = tid % (DIM / 4);
        int s = idx[row0 + r];
        reinterpret_cast<float4*>(&se1[r * DIM])[q] =
            reinterpret_cast<const float4*>(&emb1[(size_t)s * DIM])[q];
        reinterpret_cast<float4*>(&se2[r * DIM])[q] =
            reinterpret_cast<const float4*>(&emb2[(size_t)s * DIM])[q];
    }
    if (tid == 0) s_done = 0;
    __syncthreads();

    // ---- 3: compute own-row P/Q (8 rows x 40 d x 2 mats = 640 outputs) ----
    for (int e = tid; e < 2 * RPB * DIM; e += 256) {
        int m = e / (RPB * DIM);
        int r = (e % (RPB * DIM)) / DIM;
        int d = e % DIM;
        const float* ee = m ? &se2[r * DIM] : &se1[r * DIM];
        const float* ww = m ? &sW2t[0]      : &sW1t[0];
        float z = 0.f;
#pragma unroll
        for (int k = 0; k < DIM; k++) z = fmaf(ee[k], ww[k * DIM + d], z);
        float v = xla_tanh(ALPHA * (z + sb2[m * DIM + d]));
        if (m) sQo[r][d] = v; else sPo[r][d] = v;
    }
    __syncthreads();

    float rP[DIM], rQ[DIM];
#pragma unroll
    for (int k = 0; k < DIM; k++) { rP[k] = sPo[w][k]; rQ[k] = sQo[w][k]; }

    // ---- 4: tile loop: gather emb, compute tile P/Q, scan, early exit ----
    const float C = xla_tanh(8.0f);
    int  hits = 0;
    bool done = false;
    const int ntiles = (N_NODES + JTILE - 1) / JTILE;

    for (int t = 0; t < ntiles; t++) {
        const int j0 = t * JTILE;

        if (tid < JTILE)
            sidx[tid] = (j0 + tid < N_NODES) ? idx[j0 + tid] : 0;
        __syncthreads();

        // gather 64 emb rows (float4), OOB -> 0
        for (int e = tid; e < JTILE * (DIM / 4); e += 256) {
            int j = e / (DIM / 4), q = e % (DIM / 4);
            float4 v1 = make_float4(0.f, 0.f, 0.f, 0.f), v2 = v1;
            if (j0 + j < N_NODES) {
                int s = sidx[j];
                v1 = reinterpret_cast<const float4*>(&emb1[(size_t)s * DIM])[q];
                v2 = reinterpret_cast<const float4*>(&emb2[(size_t)s * DIM])[q];
            }
            reinterpret_cast<float4*>(&A[j * DIM])[q] = v1;
            reinterpret_cast<float4*>(&B[j * DIM])[q] = v2;
        }
        __syncthreads();

        // compute tile P/Q: 2560 outputs each, 10 per thread, into registers
        float accP[10], accQ[10];
#pragma unroll
        for (int i = 0; i < 10; i++) {
            int o = tid + i * 256;
            int j = o / DIM, d = o % DIM;
            float z1 = 0.f, z2 = 0.f;
#pragma unroll
            for (int k = 0; k < DIM; k++) {
                z1 = fmaf(A[j * DIM + k], sW1t[k * DIM + d], z1);
                z2 = fmaf(B[j * DIM + k], sW2t[k * DIM + d], z2);
            }
            accP[i] = xla_tanh(ALPHA * (z1 + sb2[d]));
            accQ[i] = xla_tanh(ALPHA * (z2 + sb2[DIM + d]));
        }
        __syncthreads();   // all reads of te done before overwrite
#pragma unroll
        for (int i = 0; i < 10; i++) {
            int o = tid + i * 256;
            int j = o / DIM, d = o % DIM;
            A[d * TPAD + j] = accP[i];     // tP [d][j]
            B[d * TPAD + j] = accQ[i];     // tQ [d][j]
        }
        __syncthreads();

        // scan: one warp per row, 64 columns in 2 quads
        if (!done) {
#pragma unroll
            for (int q = 0; q < JTILE / 32; q++) {
                const int jt = q * 32 + lane;
                const int j  = j0 + jt;
                float d1 = 0.f, d2 = 0.f;
#pragma unroll
                for (int k = 0; k < DIM; k++) {
                    d1 = fmaf(rP[k], B[k * TPAD + jt], d1);   // <P_i, Q_j>
                    d2 = fmaf(rQ[k], A[k * TPAD + jt], d2);   // <Q_i, P_j>
                }
                float a   = d1 - d2;
                float val = xla_tanh(ALPHA * a);
                bool pred = (j < N_NODES) && (val >= C);
                unsigned m = __ballot_sync(0xffffffffu, pred);
                int rank = __popc(m & ((1u << lane) - 1u));
                if (pred && (hits + rank) < KSEL)
                    out[(size_t)row * N_NODES + j] = val;     // own row, already zeroed
                hits += __popc(m);
                if (hits >= KSEL) break;
            }
            if (hits >= KSEL) {
                done = true;
                if (lane == 0) atomicAdd(&s_done, 1);
            }
        }
        __syncthreads();
        if (s_done == RPB) break;
    }

    if (hits < KSEL && lane == 0) {
        int slot = atomicAdd(&g_nfail, 1);
        g_fail[slot] = row;
    }
}

// ---------------- fallback: exact stable top-32, recompute P/Q (expected no-op) ----------------
__global__ void __launch_bounds__(256) fallback_kernel(
        const int* __restrict__ idx,
        const float* __restrict__ emb1,
        const float* __restrict__ emb2,
        const float* __restrict__ W1,
        const float* __restrict__ b1,
        const float* __restrict__ W2,
        const float* __restrict__ b2,
        float* __restrict__ out) {
    const int nfail = g_nfail;
    if (nfail == 0) return;

    const int tid = threadIdx.x, lane = tid & 31, w = tid >> 5;
    constexpr int CPT = (N_NODES + 255) / 256;

    __shared__ float sW1t[DIM * DIM];
    __shared__ float sW2t[DIM * DIM];
    __shared__ float sb2[2 * DIM];
    __shared__ unsigned long long warpmax[8];
    __shared__ unsigned long long s_best;
    __shared__ float srP[DIM], srQ[DIM];

    for (int e = tid; e < DIM * DIM; e += 256) {
        int d = e / DIM, k = e % DIM;
        sW1t[k * DIM + d] = W1[e];
        sW2t[k * DIM + d] = W2[e];
    }
    if (tid < 2 * DIM)
        sb2[tid] = (tid < DIM) ? b1[tid] : b2[tid - DIM];
    __syncthreads();

    for (int t = 0; t < nfail; t++) {
        const int frow = g_fail[t];
        // compute this row's P/Q vectors
        if (tid < 2 * DIM) {
            int m = tid / DIM, d = tid % DIM;
            int s = idx[frow];
            const float* eb = m ? emb2 : emb1;
            const float* ww = m ? sW2t : sW1t;
            float z = 0.f;
            for (int k = 0; k < DIM; k++)
                z = fmaf(eb[(size_t)s * DIM + k], ww[k * DIM + d], z);
            float v = xla_tanh(ALPHA * (z + sb2[m * DIM + d]));
            if (m) srQ[d] = v; else srP[d] = v;
        }
        __syncthreads();

        float rP[DIM], rQ[DIM];
#pragma unroll
        for (int k = 0; k < DIM; k++) { rP[k] = srP[k]; rQ[k] = srQ[k]; }

        float vals[CPT];
#pragma unroll
        for (int c = 0; c < CPT; c++) {
            int j = tid + c * 256;
            float v = -1.f;
            if (j < N_NODES) {
                int s = idx[j];
                float pj[DIM], qj[DIM];
                for (int d = 0; d < DIM; d++) {
                    float z1 = 0.f, z2 = 0.f;
                    for (int k = 0; k < DIM; k++) {
                        z1 = fmaf(emb1[(size_t)s * DIM + k], sW1t[k * DIM + d], z1);
                        z2 = fmaf(emb2[(size_t)s * DIM + k], sW2t[k * DIM + d], z2);
                    }
                    pj[d] = xla_tanh(ALPHA * (z1 + sb2[d]));
                    qj[d] = xla_tanh(ALPHA * (z2 + sb2[DIM + d]));
                }
                float d1 = 0.f, d2 = 0.f;
                for (int k = 0; k < DIM; k++) {
                    d1 = fmaf(rP[k], qj[k], d1);
                    d2 = fmaf(rQ[k], pj[k], d2);
                }
                v = fmaxf(0.f, xla_tanh(ALPHA * (d1 - d2)));
            }
            vals[c] = v;
        }

        unsigned long long chosen = 0ull;
        for (int it = 0; it < KSEL; it++) {
            unsigned long long best = 0ull;
#pragma unroll
            for (int c = 0; c < CPT; c++) {
                int j = tid + c * 256;
                if (j < N_NODES && !((chosen >> c) & 1ull) && vals[c] >= 0.f) {
                    unsigned long long key =
                        ((unsigned long long)__float_as_uint(vals[c]) << 32) |
                        (unsigned long long)(0xFFFFFFFFu - (unsigned)j);
                    if (key > best) best = key;
                }
            }
#pragma unroll
            for (int off = 16; off > 0; off >>= 1) {
                unsigned long long o = __shfl_down_sync(0xffffffffu, best, off);
                if (o > best) best = o;
            }
            if (lane == 0) warpmax[w] = best;
            __syncthreads();
            if (tid == 0) {
                unsigned long long b = warpmax[0];
                for (int i = 1; i < 8; i++) if (warpmax[i] > b) b = warpmax[i];
                s_best = b;
            }
            __syncthreads();
            unsigned long long gb = s_best;
            int widx = (int)(0xFFFFFFFFu - (unsigned)(gb & 0xFFFFFFFFu));
            if ((widx & 255) == tid) {
                chosen |= 1ull << (widx >> 8);
                out[(size_t)frow * N_NODES + widx] = __uint_as_float((unsigned)(gb >> 32));
            }
            __syncthreads();
        }
        __syncthreads();
    }
    __syncthreads();
    if (tid == 0) g_nfail = 0;   // reset for next replay
}

// ---------------- launch ----------------
extern "C" void kernel_launch(void* const* d_in, const int* in_sizes, int n_in,
                              void* d_out, int out_size) {
    const int*   idx  = (const int*)  d_in[0];
    const float* emb1 = (const float*)d_in[1];
    const float* emb2 = (const float*)d_in[2];
    const float* W1   = (const float*)d_in[3];
    const float* b1   = (const float*)d_in[4];
    const float* W2   = (const float*)d_in[5];
    const float* b2   = (const float*)d_in[6];
    float* out = (float*)d_out;

    (void)in_sizes; (void)n_in; (void)out_size;

    mega_kernel<<<NGROUPS, 256>>>(idx, emb1, emb2, W1, b1, W2, b2, out);
    fallback_kernel<<<1, 256>>>(idx, emb1, emb2, W1, b1, W2, b2, out);
}

// round 10
// speedup vs baseline: 2.5108x; 2.5108x over previous
#include <cuda_runtime.h>
#include <stdint.h>
#include <stddef.h>

#define N_NODES 10000
#define DIM 40
#define KSEL 32
#define ALPHA 3.0f
#define JTILE 64
#define RPB 8                      // rows per mega block (one warp per row)
#define NGROUPS (N_NODES / RPB)    // 1250
#define PGRID 296                  // prep persistent blocks
#define PCROWS 16                  // prep rows per chunk
#define NPCH ((N_NODES + PCROWS - 1) / PCROWS)   // 625 chunks

// ---------------- device scratch (no allocation allowed) ----------------
__device__ float g_P[N_NODES * DIM];
__device__ float g_Q[N_NODES * DIM];
__device__ int   g_fail[N_NODES];
__device__ int   g_nfail = 0;
__device__ int   g_c2    = 0;     // mega blocks completed

// ---------------- XLA EmitFastTanh replica (with-FMA variant) ----------------
__device__ __forceinline__ float xla_tanh(float x) {
    const float kClamp = 7.99881172180175781f;
    float ax = fabsf(x);
    float xc = fminf(fmaxf(x, -kClamp), kClamp);
    float x2 = xc * xc;
    float num = -2.76076847742355e-16f;
    num = fmaf(x2, num,  2.00018790482477e-13f);
    num = fmaf(x2, num, -8.60467152213735e-11f);
    num = fmaf(x2, num,  5.12229709037114e-08f);
    num = fmaf(x2, num,  1.48572235717979e-05f);
    num = fmaf(x2, num,  6.37261928875436e-04f);
    num = fmaf(x2, num,  4.89352455891786e-03f);
    num = xc * num;
    float den = 1.19825839466702e-06f;
    den = fmaf(x2, den, 1.18534705686654e-04f);
    den = fmaf(x2, den, 2.26843463243900e-03f);
    den = fmaf(x2, den, 4.89352518554385e-03f);
    float r = num / den;
    return (ax < 0.0004f) ? x : r;
}

// ---------------- kernel 1: prep — persistent blocks, W staged once ----------------
__global__ void __launch_bounds__(256) prep_kernel(
        const int* __restrict__ idx,
        const float* __restrict__ emb1,
        const float* __restrict__ emb2,
        const float* __restrict__ W1,
        const float* __restrict__ b1,
        const float* __restrict__ W2,
        const float* __restrict__ b2) {
    __shared__ __align__(16) float sW1t[DIM * DIM];   // [k][d]
    __shared__ __align__(16) float sW2t[DIM * DIM];
    __shared__ float sb2[2 * DIM];
    __shared__ __align__(16) float se1[PCROWS * DIM];
    __shared__ __align__(16) float se2[PCROWS * DIM];
    __shared__ int sidx[PCROWS];

    const int tid = threadIdx.x;

    for (int e = tid; e < DIM * DIM; e += 256) {
        int d = e / DIM, k = e % DIM;
        sW1t[k * DIM + d] = W1[e];
        sW2t[k * DIM + d] = W2[e];
    }
    if (tid < 2 * DIM)
        sb2[tid] = (tid < DIM) ? b1[tid] : b2[tid - DIM];
    __syncthreads();

    for (int c = blockIdx.x; c < NPCH; c += PGRID) {
        const int pr0 = c * PCROWS;
        int nr = N_NODES - pr0; if (nr > PCROWS) nr = PCROWS;

        if (tid < nr) sidx[tid] = idx[pr0 + tid];
        __syncthreads();
        // stage e rows: nr*10 float4 per matrix
        for (int e = tid; e < nr * (DIM / 4); e += 256) {
            int r = e / (DIM / 4), q = e % (DIM / 4);
            int s = sidx[r];
            reinterpret_cast<float4*>(&se1[r * DIM])[q] =
                reinterpret_cast<const float4*>(&emb1[(size_t)s * DIM])[q];
            reinterpret_cast<float4*>(&se2[r * DIM])[q] =
                reinterpret_cast<const float4*>(&emb2[(size_t)s * DIM])[q];
        }
        __syncthreads();

        // tasks: (matrix m, row r, dgroup dg) = nr*10*2 <= 320
        for (int task = tid; task < nr * (DIM / 4) * 2; task += 256) {
            int m  = task / (nr * (DIM / 4));
            int rr = (task % (nr * (DIM / 4))) / (DIM / 4);
            int dg = (task % (DIM / 4)) * 4;
            const float* ee = m ? &se2[rr * DIM] : &se1[rr * DIM];
            const float* ww = m ? sW2t : sW1t;
            float za = 0.f, zb = 0.f, zc = 0.f, zd = 0.f;
#pragma unroll
            for (int k = 0; k < DIM; k++) {
                float ev = ee[k];
                float4 wv = *reinterpret_cast<const float4*>(&ww[k * DIM + dg]);
                za = fmaf(ev, wv.x, za); zb = fmaf(ev, wv.y, zb);
                zc = fmaf(ev, wv.z, zc); zd = fmaf(ev, wv.w, zd);
            }
            float4 o;
            o.x = xla_tanh(ALPHA * (za + sb2[m * DIM + dg + 0]));
            o.y = xla_tanh(ALPHA * (zb + sb2[m * DIM + dg + 1]));
            o.z = xla_tanh(ALPHA * (zc + sb2[m * DIM + dg + 2]));
            o.w = xla_tanh(ALPHA * (zd + sb2[m * DIM + dg + 3]));
            float* dst = m ? &g_Q[(pr0 + rr) * DIM + dg] : &g_P[(pr0 + rr) * DIM + dg];
            *reinterpret_cast<float4*>(dst) = o;
        }
        __syncthreads();
    }
}

// ---------------- kernel 2: mega — zero own rows + scan + scatter (+ last-block fallback) ----------------
__global__ void __launch_bounds__(256, 2) mega_kernel(float* __restrict__ out) {
    __shared__ float sP[RPB][DIM];
    __shared__ float sQ[RPB][DIM];
    __shared__ float tP[DIM][JTILE];
    __shared__ float tQ[DIM][JTILE];
    __shared__ int s_done, s_last;
    __shared__ unsigned long long warpmax[8];
    __shared__ unsigned long long s_best;

    const int tid  = threadIdx.x;
    const int lane = tid & 31;
    const int w    = tid >> 5;
    const int row0 = blockIdx.x * RPB;
    const int row  = row0 + w;

    // zero this block's 8 output rows (contiguous 20000 float4)
    {
        float4* o4 = reinterpret_cast<float4*>(out + (size_t)row0 * N_NODES);
        const float4 z = make_float4(0.f, 0.f, 0.f, 0.f);
        for (int i = tid; i < RPB * N_NODES / 4; i += 256)
            __stcs(&o4[i], z);
    }

    // stage own-row vectors
    for (int e = tid; e < RPB * DIM; e += 256) {
        int r = e / DIM, k = e % DIM;
        sP[r][k] = g_P[(row0 + r) * DIM + k];
        sQ[r][k] = g_Q[(row0 + r) * DIM + k];
    }
    if (tid == 0) s_done = 0;
    __syncthreads();

    float rP[DIM], rQ[DIM];
#pragma unroll
    for (int k = 0; k < DIM; k++) { rP[k] = sP[w][k]; rQ[k] = sQ[w][k]; }

    const float C = xla_tanh(8.0f);
    int  hits = 0;
    bool done = false;
    const int ntiles = (N_NODES + JTILE - 1) / JTILE;

    for (int t = 0; t < ntiles; t++) {
        const int j0 = t * JTILE;
        for (int e = tid; e < DIM * JTILE; e += 256) {
            int k = e / JTILE, j = e % JTILE;
            int gj = j0 + j;
            float vp = 0.f, vq = 0.f;
            if (gj < N_NODES) {
                vp = g_P[gj * DIM + k];
                vq = g_Q[gj * DIM + k];
            }
            tP[k][j] = vp;
            tQ[k][j] = vq;
        }
        __syncthreads();

        if (!done) {
#pragma unroll
            for (int q = 0; q < JTILE / 32; q++) {
                const int jt = q * 32 + lane;
                const int j  = j0 + jt;
                float d1 = 0.f, d2 = 0.f;
#pragma unroll
                for (int k = 0; k < DIM; k++) {
                    d1 = fmaf(rP[k], tQ[k][jt], d1);
                    d2 = fmaf(rQ[k], tP[k][jt], d2);
                }
                float a   = d1 - d2;
                float val = xla_tanh(ALPHA * a);
                bool pred = (j < N_NODES) && (val >= C);
                unsigned m = __ballot_sync(0xffffffffu, pred);
                int rank = __popc(m & ((1u << lane) - 1u));
                if (pred && (hits + rank) < KSEL)
                    out[(size_t)row * N_NODES + j] = val;   // own row, already zeroed
                hits += __popc(m);
                if (hits >= KSEL) break;
            }
            if (hits >= KSEL) {
                done = true;
                if (lane == 0) atomicAdd(&s_done, 1);
            }
        }
        __syncthreads();
        if (s_done == RPB) break;
    }

    if (hits < KSEL && lane == 0) {
        int slot = atomicAdd(&g_nfail, 1);
        g_fail[slot] = row;
    }

    // ---- completion: last block runs exact fallback (expected no-op) ----
    __threadfence();
    __syncthreads();
    if (tid == 0) {
        int t = atomicAdd(&g_c2, 1);
        s_last = (t == NGROUPS - 1) ? 1 : 0;
    }
    __syncthreads();
    if (!s_last) return;

    __threadfence();
    const int nfail = *(volatile int*)&g_nfail;
    if (nfail > 0) {
        constexpr int CPT = (N_NODES + 255) / 256;
        for (int t = 0; t < nfail; t++) {
            const int frow = g_fail[t];
            float fP[DIM], fQ[DIM];
#pragma unroll
            for (int k = 0; k < DIM; k++) {
                fP[k] = g_P[frow * DIM + k];
                fQ[k] = g_Q[frow * DIM + k];
            }
            float vals[CPT];
#pragma unroll
            for (int c = 0; c < CPT; c++) {
                int j = tid + c * 256;
                float v = -1.f;
                if (j < N_NODES) {
                    float d1 = 0.f, d2 = 0.f;
                    for (int k = 0; k < DIM; k++) {
                        d1 = fmaf(fP[k], g_Q[j * DIM + k], d1);
                        d2 = fmaf(fQ[k], g_P[j * DIM + k], d2);
                    }
                    v = fmaxf(0.f, xla_tanh(ALPHA * (d1 - d2)));
                }
                vals[c] = v;
            }
            unsigned long long chosen = 0ull;
            for (int it = 0; it < KSEL; it++) {
                unsigned long long best = 0ull;
#pragma unroll
                for (int c = 0; c < CPT; c++) {
                    int j = tid + c * 256;
                    if (j < N_NODES && !((chosen >> c) & 1ull) && vals[c] >= 0.f) {
                        unsigned long long key =
                            ((unsigned long long)__float_as_uint(vals[c]) << 32) |
                            (unsigned long long)(0xFFFFFFFFu - (unsigned)j);
                        if (key > best) best = key;
                    }
                }
#pragma unroll
                for (int off = 16; off > 0; off >>= 1) {
                    unsigned long long o = __shfl_down_sync(0xffffffffu, best, off);
                    if (o > best) best = o;
                }
                if (lane == 0) warpmax[w] = best;
                __syncthreads();
                if (tid == 0) {
                    unsigned long long b = warpmax[0];
                    for (int i = 1; i < 8; i++) if (warpmax[i] > b) b = warpmax[i];
                    s_best = b;
                }
                __syncthreads();
                unsigned long long gb = s_best;
                int widx = (int)(0xFFFFFFFFu - (unsigned)(gb & 0xFFFFFFFFu));
                if ((widx & 255) == tid) {
                    chosen |= 1ull << (widx >> 8);
                    out[(size_t)frow * N_NODES + widx] = __uint_as_float((unsigned)(gb >> 32));
                }
                __syncthreads();
            }
            __syncthreads();
        }
    }
    // reset for next graph replay
    __syncthreads();
    if (tid == 0) { g_nfail = 0; g_c2 = 0; }
}

// ---------------- launch ----------------
extern "C" void kernel_launch(void* const* d_in, const int* in_sizes, int n_in,
                              void* d_out, int out_size) {
    const int*   idx  = (const int*)  d_in[0];
    const float* emb1 = (const float*)d_in[1];
    const float* emb2 = (const float*)d_in[2];
    const float* W1   = (const float*)d_in[3];
    const float* b1   = (const float*)d_in[4];
    const float* W2   = (const float*)d_in[5];
    const float* b2   = (const float*)d_in[6];
    float* out = (float*)d_out;

    (void)in_sizes; (void)n_in; (void)out_size;

    prep_kernel<<<PGRID, 256>>>(idx, emb1, emb2, W1, b1, W2, b2);
    mega_kernel<<<NGROUPS, 256>>>(out);
}

// round 11
// speedup vs baseline: 2.8560x; 1.1375x over previous
#include <cuda_runtime.h>
#include <stdint.h>
#include <stddef.h>

#define N_NODES 10000
#define DIM 40
#define KSEL 32
#define ALPHA 3.0f
#define JTILE 64
#define RPB 8                      // rows per mega block (one warp per row)
#define NGROUPS (N_NODES / RPB)    // 1250
#define PGRID 296                  // prep persistent blocks
#define PCROWS 16                  // prep rows per chunk
#define NPCH ((N_NODES + PCROWS - 1) / PCROWS)   // 625 chunks

// ---------------- device scratch (no allocation allowed) ----------------
__device__ float g_P[N_NODES * DIM];
__device__ float g_Q[N_NODES * DIM];
__device__ int   g_fail[N_NODES];
__device__ int   g_nfail = 0;

// ---------------- XLA EmitFastTanh replica (with-FMA variant) ----------------
__device__ __forceinline__ float xla_tanh(float x) {
    const float kClamp = 7.99881172180175781f;
    float ax = fabsf(x);
    float xc = fminf(fmaxf(x, -kClamp), kClamp);
    float x2 = xc * xc;
    float num = -2.76076847742355e-16f;
    num = fmaf(x2, num,  2.00018790482477e-13f);
    num = fmaf(x2, num, -8.60467152213735e-11f);
    num = fmaf(x2, num,  5.12229709037114e-08f);
    num = fmaf(x2, num,  1.48572235717979e-05f);
    num = fmaf(x2, num,  6.37261928875436e-04f);
    num = fmaf(x2, num,  4.89352455891786e-03f);
    num = xc * num;
    float den = 1.19825839466702e-06f;
    den = fmaf(x2, den, 1.18534705686654e-04f);
    den = fmaf(x2, den, 2.26843463243900e-03f);
    den = fmaf(x2, den, 4.89352518554385e-03f);
    float r = num / den;
    return (ax < 0.0004f) ? x : r;
}

// ---------------- kernel 1: prep — persistent blocks, W staged once (R10, proven ~9us) ----------------
__global__ void __launch_bounds__(256) prep_kernel(
        const int* __restrict__ idx,
        const float* __restrict__ emb1,
        const float* __restrict__ emb2,
        const float* __restrict__ W1,
        const float* __restrict__ b1,
        const float* __restrict__ W2,
        const float* __restrict__ b2) {
    __shared__ __align__(16) float sW1t[DIM * DIM];   // [k][d]
    __shared__ __align__(16) float sW2t[DIM * DIM];
    __shared__ float sb2[2 * DIM];
    __shared__ __align__(16) float se1[PCROWS * DIM];
    __shared__ __align__(16) float se2[PCROWS * DIM];
    __shared__ int sidx[PCROWS];

    const int tid = threadIdx.x;

    if (blockIdx.x == 0 && tid == 0) g_nfail = 0;

    for (int e = tid; e < DIM * DIM; e += 256) {
        int d = e / DIM, k = e % DIM;
        sW1t[k * DIM + d] = W1[e];
        sW2t[k * DIM + d] = W2[e];
    }
    if (tid < 2 * DIM)
        sb2[tid] = (tid < DIM) ? b1[tid] : b2[tid - DIM];
    __syncthreads();

    for (int c = blockIdx.x; c < NPCH; c += PGRID) {
        const int pr0 = c * PCROWS;
        int nr = N_NODES - pr0; if (nr > PCROWS) nr = PCROWS;

        if (tid < nr) sidx[tid] = idx[pr0 + tid];
        __syncthreads();
        for (int e = tid; e < nr * (DIM / 4); e += 256) {
            int r = e / (DIM / 4), q = e % (DIM / 4);
            int s = sidx[r];
            reinterpret_cast<float4*>(&se1[r * DIM])[q] =
                reinterpret_cast<const float4*>(&emb1[(size_t)s * DIM])[q];
            reinterpret_cast<float4*>(&se2[r * DIM])[q] =
                reinterpret_cast<const float4*>(&emb2[(size_t)s * DIM])[q];
        }
        __syncthreads();

        for (int task = tid; task < nr * (DIM / 4) * 2; task += 256) {
            int m  = task / (nr * (DIM / 4));
            int rr = (task % (nr * (DIM / 4))) / (DIM / 4);
            int dg = (task % (DIM / 4)) * 4;
            const float* ee = m ? &se2[rr * DIM] : &se1[rr * DIM];
            const float* ww = m ? sW2t : sW1t;
            float za = 0.f, zb = 0.f, zc = 0.f, zd = 0.f;
#pragma unroll
            for (int k = 0; k < DIM; k++) {
                float ev = ee[k];
                float4 wv = *reinterpret_cast<const float4*>(&ww[k * DIM + dg]);
                za = fmaf(ev, wv.x, za); zb = fmaf(ev, wv.y, zb);
                zc = fmaf(ev, wv.z, zc); zd = fmaf(ev, wv.w, zd);
            }
            float4 o;
            o.x = xla_tanh(ALPHA * (za + sb2[m * DIM + dg + 0]));
            o.y = xla_tanh(ALPHA * (zb + sb2[m * DIM + dg + 1]));
            o.z = xla_tanh(ALPHA * (zc + sb2[m * DIM + dg + 2]));
            o.w = xla_tanh(ALPHA * (zd + sb2[m * DIM + dg + 3]));
            float* dst = m ? &g_Q[(pr0 + rr) * DIM + dg] : &g_P[(pr0 + rr) * DIM + dg];
            *reinterpret_cast<float4*>(dst) = o;
        }
        __syncthreads();
    }
}

// ---------------- kernel 2: mega — EXACT R5 version (zero own rows + scan + scatter) ----------------
__global__ void __launch_bounds__(RPB * 32) mega_kernel(float* __restrict__ out) {
    __shared__ float sP[RPB][DIM];
    __shared__ float sQ[RPB][DIM];
    __shared__ float tP[DIM][JTILE];
    __shared__ float tQ[DIM][JTILE];
    __shared__ int s_done;

    const int tid  = threadIdx.x;
    const int lane = tid & 31;
    const int w    = tid >> 5;
    const int row0 = blockIdx.x * RPB;
    const int row  = row0 + w;

    // zero this block's 8 output rows (contiguous 80000 floats = 20000 float4)
    {
        float4* o4 = reinterpret_cast<float4*>(out + (size_t)row0 * N_NODES);
        const float4 z = make_float4(0.f, 0.f, 0.f, 0.f);
        for (int i = tid; i < RPB * N_NODES / 4; i += RPB * 32)
            __stcs(&o4[i], z);
    }

    // stage own-row vectors
    for (int e = tid; e < RPB * DIM; e += RPB * 32) {
        int r = e / DIM, k = e % DIM;
        sP[r][k] = g_P[(row0 + r) * DIM + k];
        sQ[r][k] = g_Q[(row0 + r) * DIM + k];
    }
    if (tid == 0) s_done = 0;
    __syncthreads();   // zeros done + staging done before any scan write

    float rP[DIM], rQ[DIM];
#pragma unroll
    for (int k = 0; k < DIM; k++) { rP[k] = sP[w][k]; rQ[k] = sQ[w][k]; }

    const float C = xla_tanh(8.0f);
    int  hits = 0;
    bool done = false;
    const int ntiles = (N_NODES + JTILE - 1) / JTILE;

    for (int t = 0; t < ntiles; t++) {
        const int j0 = t * JTILE;
        for (int e = tid; e < DIM * JTILE; e += RPB * 32) {
            int k = e / JTILE, j = e % JTILE;
            int gj = j0 + j;
            float vp = 0.f, vq = 0.f;
            if (gj < N_NODES) {
                vp = g_P[gj * DIM + k];
                vq = g_Q[gj * DIM + k];
            }
            tP[k][j] = vp;
            tQ[k][j] = vq;
        }
        __syncthreads();

        if (!done) {
#pragma unroll
            for (int q = 0; q < JTILE / 32; q++) {
                const int jt = q * 32 + lane;
                const int j  = j0 + jt;
                float d1 = 0.f, d2 = 0.f;
#pragma unroll
                for (int k = 0; k < DIM; k++) {
                    d1 = fmaf(rP[k], tQ[k][jt], d1);
                    d2 = fmaf(rQ[k], tP[k][jt], d2);
                }
                float a   = d1 - d2;
                float val = xla_tanh(ALPHA * a);
                bool pred = (j < N_NODES) && (val >= C);
                unsigned m = __ballot_sync(0xffffffffu, pred);
                int rank = __popc(m & ((1u << lane) - 1u));
                if (pred && (hits + rank) < KSEL)
                    out[(size_t)row * N_NODES + j] = val;   // own row, already zeroed
                hits += __popc(m);
                if (hits >= KSEL) break;
            }
            if (hits >= KSEL) {
                done = true;
                if (lane == 0) atomicAdd(&s_done, 1);
            }
        }
        __syncthreads();
        if (s_done == RPB) break;
    }

    if (hits < KSEL && lane == 0) {
        int slot = atomicAdd(&g_nfail, 1);
        g_fail[slot] = row;
    }
}

// ---------------- kernel 3: exact stable top-32 fallback (single block, expected no-op) ----------------
__global__ void __launch_bounds__(256) fallback_kernel(float* __restrict__ out) {
    const int tid = threadIdx.x, lane = tid & 31, w = tid >> 5;
    constexpr int CPT = (N_NODES + 255) / 256;

    __shared__ unsigned long long warpmax[8];
    __shared__ unsigned long long s_best;

    const int nfail = g_nfail;
    for (int t = 0; t < nfail; t++) {
        const int frow = g_fail[t];
        float rP[DIM], rQ[DIM];
#pragma unroll
        for (int k = 0; k < DIM; k++) {
            rP[k] = g_P[frow * DIM + k];
            rQ[k] = g_Q[frow * DIM + k];
        }
        float vals[CPT];
#pragma unroll
        for (int c = 0; c < CPT; c++) {
            int j = tid + c * 256;
            float v = -1.f;
            if (j < N_NODES) {
                float d1 = 0.f, d2 = 0.f;
                for (int k = 0; k < DIM; k++) {
                    d1 = fmaf(rP[k], g_Q[j * DIM + k], d1);
                    d2 = fmaf(rQ[k], g_P[j * DIM + k], d2);
                }
                v = fmaxf(0.f, xla_tanh(ALPHA * (d1 - d2)));
            }
            vals[c] = v;
        }
        unsigned long long chosen = 0ull;
        for (int it = 0; it < KSEL; it++) {
            unsigned long long best = 0ull;
#pragma unroll
            for (int c = 0; c < CPT; c++) {
                int j = tid + c * 256;
                if (j < N_NODES && !((chosen >> c) & 1ull) && vals[c] >= 0.f) {
                    unsigned long long key =
                        ((unsigned long long)__float_as_uint(vals[c]) << 32) |
                        (unsigned long long)(0xFFFFFFFFu - (unsigned)j);
                    if (key > best) best = key;
                }
            }
#pragma unroll
            for (int off = 16; off > 0; off >>= 1) {
                unsigned long long o = __shfl_down_sync(0xffffffffu, best, off);
                if (o > best) best = o;
            }
            if (lane == 0) warpmax[w] = best;
            __syncthreads();
            if (tid == 0) {
                unsigned long long b = warpmax[0];
                for (int i = 1; i < 8; i++) if (warpmax[i] > b) b = warpmax[i];
                s_best = b;
            }
            __syncthreads();
            unsigned long long gb = s_best;
            int widx = (int)(0xFFFFFFFFu - (unsigned)(gb & 0xFFFFFFFFu));
            if ((widx & 255) == tid) {
                chosen |= 1ull << (widx >> 8);
                out[(size_t)frow * N_NODES + widx] = __uint_as_float((unsigned)(gb >> 32));
            }
            __syncthreads();
        }
        __syncthreads();
    }
    __syncthreads();
    if (tid == 0) g_nfail = 0;   // reset for next replay
}

// ---------------- launch ----------------
extern "C" void kernel_launch(void* const* d_in, const int* in_sizes, int n_in,
                              void* d_out, int out_size) {
    const int*   idx  = (const int*)  d_in[0];
    const float* emb1 = (const float*)d_in[1];
    const float* emb2 = (const float*)d_in[2];
    const float* W1   = (const float*)d_in[3];
    const float* b1   = (const float*)d_in[4];
    const float* W2   = (const float*)d_in[5];
    const float* b2   = (const float*)d_in[6];
    float* out = (float*)d_out;

    (void)in_sizes; (void)n_in; (void)out_size;

    prep_kernel<<<PGRID, 256>>>(idx, emb1, emb2, W1, b1, W2, b2);
    mega_kernel<<<NGROUPS, 256>>>(out);
    fallback_kernel<<<1, 256>>>(out);
}

// round 12
// speedup vs baseline: 2.9358x; 1.0279x over previous
#include <cuda_runtime.h>
#include <stdint.h>
#include <stddef.h>

#define N_NODES 10000
#define DIM 40
#define KSEL 32
#define ALPHA 3.0f
#define JTILE 64
#define RPB 8                      // rows per mega block (one warp per row)
#define NGROUPS (N_NODES / RPB)    // 1250
#define PGRID 296                  // prep persistent blocks
#define PCROWS 16                  // prep rows per chunk
#define NPCH ((N_NODES + PCROWS - 1) / PCROWS)   // 625 chunks

// ---------------- device scratch (no allocation allowed) ----------------
__device__ float g_P[N_NODES * DIM];
__device__ float g_Q[N_NODES * DIM];
__device__ int   g_fail[N_NODES];
__device__ int   g_nfail = 0;

// ---------------- XLA EmitFastTanh replica (with-FMA variant) ----------------
__device__ __forceinline__ float xla_tanh(float x) {
    const float kClamp = 7.99881172180175781f;
    float ax = fabsf(x);
    float xc = fminf(fmaxf(x, -kClamp), kClamp);
    float x2 = xc * xc;
    float num = -2.76076847742355e-16f;
    num = fmaf(x2, num,  2.00018790482477e-13f);
    num = fmaf(x2, num, -8.60467152213735e-11f);
    num = fmaf(x2, num,  5.12229709037114e-08f);
    num = fmaf(x2, num,  1.48572235717979e-05f);
    num = fmaf(x2, num,  6.37261928875436e-04f);
    num = fmaf(x2, num,  4.89352455891786e-03f);
    num = xc * num;
    float den = 1.19825839466702e-06f;
    den = fmaf(x2, den, 1.18534705686654e-04f);
    den = fmaf(x2, den, 2.26843463243900e-03f);
    den = fmaf(x2, den, 4.89352518554385e-03f);
    float r = num / den;
    return (ax < 0.0004f) ? x : r;
}

// ---------------- kernel 1: prep — persistent, triggers PDL at start ----------------
__global__ void __launch_bounds__(256) prep_kernel(
        const int* __restrict__ idx,
        const float* __restrict__ emb1,
        const float* __restrict__ emb2,
        const float* __restrict__ W1,
        const float* __restrict__ b1,
        const float* __restrict__ W2,
        const float* __restrict__ b2) {
    // allow the dependent (mega) grid to launch immediately; it self-gates
    // with cudaGridDependencySynchronize() before reading g_P/g_Q.
    cudaTriggerProgrammaticLaunchCompletion();

    __shared__ __align__(16) float sW1t[DIM * DIM];   // [k][d]
    __shared__ __align__(16) float sW2t[DIM * DIM];
    __shared__ float sb2[2 * DIM];
    __shared__ __align__(16) float se1[PCROWS * DIM];
    __shared__ __align__(16) float se2[PCROWS * DIM];
    __shared__ int sidx[PCROWS];

    const int tid = threadIdx.x;

    if (blockIdx.x == 0 && tid == 0) g_nfail = 0;

    for (int e = tid; e < DIM * DIM; e += 256) {
        int d = e / DIM, k = e % DIM;
        sW1t[k * DIM + d] = W1[e];
        sW2t[k * DIM + d] = W2[e];
    }
    if (tid < 2 * DIM)
        sb2[tid] = (tid < DIM) ? b1[tid] : b2[tid - DIM];
    __syncthreads();

    for (int c = blockIdx.x; c < NPCH; c += PGRID) {
        const int pr0 = c * PCROWS;
        int nr = N_NODES - pr0; if (nr > PCROWS) nr = PCROWS;

        if (tid < nr) sidx[tid] = idx[pr0 + tid];
        __syncthreads();
        for (int e = tid; e < nr * (DIM / 4); e += 256) {
            int r = e / (DIM / 4), q = e % (DIM / 4);
            int s = sidx[r];
            reinterpret_cast<float4*>(&se1[r * DIM])[q] =
                reinterpret_cast<const float4*>(&emb1[(size_t)s * DIM])[q];
            reinterpret_cast<float4*>(&se2[r * DIM])[q] =
                reinterpret_cast<const float4*>(&emb2[(size_t)s * DIM])[q];
        }
        __syncthreads();

        for (int task = tid; task < nr * (DIM / 4) * 2; task += 256) {
            int m  = task / (nr * (DIM / 4));
            int rr = (task % (nr * (DIM / 4))) / (DIM / 4);
            int dg = (task % (DIM / 4)) * 4;
            const float* ee = m ? &se2[rr * DIM] : &se1[rr * DIM];
            const float* ww = m ? sW2t : sW1t;
            float za = 0.f, zb = 0.f, zc = 0.f, zd = 0.f;
#pragma unroll
            for (int k = 0; k < DIM; k++) {
                float ev = ee[k];
                float4 wv = *reinterpret_cast<const float4*>(&ww[k * DIM + dg]);
                za = fmaf(ev, wv.x, za); zb = fmaf(ev, wv.y, zb);
                zc = fmaf(ev, wv.z, zc); zd = fmaf(ev, wv.w, zd);
            }
            float4 o;
            o.x = xla_tanh(ALPHA * (za + sb2[m * DIM + dg + 0]));
            o.y = xla_tanh(ALPHA * (zb + sb2[m * DIM + dg + 1]));
            o.z = xla_tanh(ALPHA * (zc + sb2[m * DIM + dg + 2]));
            o.w = xla_tanh(ALPHA * (zd + sb2[m * DIM + dg + 3]));
            float* dst = m ? &g_Q[(pr0 + rr) * DIM + dg] : &g_P[(pr0 + rr) * DIM + dg];
            *reinterpret_cast<float4*>(dst) = o;
        }
        __syncthreads();
    }
}

// ---------------- kernel 2: mega — zero own rows, PDL-sync, scan + scatter ----------------
__global__ void __launch_bounds__(RPB * 32) mega_kernel(float* __restrict__ out) {
    __shared__ float sP[RPB][DIM];
    __shared__ float sQ[RPB][DIM];
    __shared__ float tP[DIM][JTILE];
    __shared__ float tQ[DIM][JTILE];
    __shared__ int s_done;

    const int tid  = threadIdx.x;
    const int lane = tid & 31;
    const int w    = tid >> 5;
    const int row0 = blockIdx.x * RPB;
    const int row  = row0 + w;

    // zero this block's 8 output rows — overlaps with the still-running prep grid
    {
        float4* o4 = reinterpret_cast<float4*>(out + (size_t)row0 * N_NODES);
        const float4 z = make_float4(0.f, 0.f, 0.f, 0.f);
        for (int i = tid; i < RPB * N_NODES / 4; i += RPB * 32)
            __stcs(&o4[i], z);
    }

    // wait for prep grid completion (memory flushed) before touching g_P/g_Q
    cudaGridDependencySynchronize();

    // stage own-row vectors
    for (int e = tid; e < RPB * DIM; e += RPB * 32) {
        int r = e / DIM, k = e % DIM;
        sP[r][k] = g_P[(row0 + r) * DIM + k];
        sQ[r][k] = g_Q[(row0 + r) * DIM + k];
    }
    if (tid == 0) s_done = 0;
    __syncthreads();   // zeros done + staging done before any scan write

    float rP[DIM], rQ[DIM];
#pragma unroll
    for (int k = 0; k < DIM; k++) { rP[k] = sP[w][k]; rQ[k] = sQ[w][k]; }

    const float C = xla_tanh(8.0f);
    int  hits = 0;
    bool done = false;
    const int ntiles = (N_NODES + JTILE - 1) / JTILE;

    for (int t = 0; t < ntiles; t++) {
        const int j0 = t * JTILE;
        for (int e = tid; e < DIM * JTILE; e += RPB * 32) {
            int k = e / JTILE, j = e % JTILE;
            int gj = j0 + j;
            float vp = 0.f, vq = 0.f;
            if (gj < N_NODES) {
                vp = g_P[gj * DIM + k];
                vq = g_Q[gj * DIM + k];
            }
            tP[k][j] = vp;
            tQ[k][j] = vq;
        }
        __syncthreads();

        if (!done) {
#pragma unroll
            for (int q = 0; q < JTILE / 32; q++) {
                const int jt = q * 32 + lane;
                const int j  = j0 + jt;
                float d1 = 0.f, d2 = 0.f;
#pragma unroll
                for (int k = 0; k < DIM; k++) {
                    d1 = fmaf(rP[k], tQ[k][jt], d1);
                    d2 = fmaf(rQ[k], tP[k][jt], d2);
                }
                float a   = d1 - d2;
                float val = xla_tanh(ALPHA * a);
                bool pred = (j < N_NODES) && (val >= C);
                unsigned m = __ballot_sync(0xffffffffu, pred);
                int rank = __popc(m & ((1u << lane) - 1u));
                if (pred && (hits + rank) < KSEL)
                    out[(size_t)row * N_NODES + j] = val;   // own row, already zeroed
                hits += __popc(m);
                if (hits >= KSEL) break;
            }
            if (hits >= KSEL) {
                done = true;
                if (lane == 0) atomicAdd(&s_done, 1);
            }
        }
        __syncthreads();
        if (s_done == RPB) break;
    }

    if (hits < KSEL && lane == 0) {
        int slot = atomicAdd(&g_nfail, 1);
        g_fail[slot] = row;
    }
}

// ---------------- kernel 3: exact stable top-32 fallback (single block, expected no-op) ----------------
__global__ void __launch_bounds__(256) fallback_kernel(float* __restrict__ out) {
    const int tid = threadIdx.x, lane = tid & 31, w = tid >> 5;
    constexpr int CPT = (N_NODES + 255) / 256;

    __shared__ unsigned long long warpmax[8];
    __shared__ unsigned long long s_best;

    const int nfail = g_nfail;
    for (int t = 0; t < nfail; t++) {
        const int frow = g_fail[t];
        float rP[DIM], rQ[DIM];
#pragma unroll
        for (int k = 0; k < DIM; k++) {
            rP[k] = g_P[frow * DIM + k];
            rQ[k] = g_Q[frow * DIM + k];
        }
        float vals[CPT];
#pragma unroll
        for (int c = 0; c < CPT; c++) {
            int j = tid + c * 256;
            float v = -1.f;
            if (j < N_NODES) {
                float d1 = 0.f, d2 = 0.f;
                for (int k = 0; k < DIM; k++) {
                    d1 = fmaf(rP[k], g_Q[j * DIM + k], d1);
                    d2 = fmaf(rQ[k], g_P[j * DIM + k], d2);
                }
                v = fmaxf(0.f, xla_tanh(ALPHA * (d1 - d2)));
            }
            vals[c] = v;
        }
        unsigned long long chosen = 0ull;
        for (int it = 0; it < KSEL; it++) {
            unsigned long long best = 0ull;
#pragma unroll
            for (int c = 0; c < CPT; c++) {
                int j = tid + c * 256;
                if (j < N_NODES && !((chosen >> c) & 1ull) && vals[c] >= 0.f) {
                    unsigned long long key =
                        ((unsigned long long)__float_as_uint(vals[c]) << 32) |
                        (unsigned long long)(0xFFFFFFFFu - (unsigned)j);
                    if (key > best) best = key;
                }
            }
#pragma unroll
            for (int off = 16; off > 0; off >>= 1) {
                unsigned long long o = __shfl_down_sync(0xffffffffu, best, off);
                if (o > best) best = o;
            }
            if (lane == 0) warpmax[w] = best;
            __syncthreads();
            if (tid == 0) {
                unsigned long long b = warpmax[0];
                for (int i = 1; i < 8; i++) if (warpmax[i] > b) b = warpmax[i];
                s_best = b;
            }
            __syncthreads();
            unsigned long long gb = s_best;
            int widx = (int)(0xFFFFFFFFu - (unsigned)(gb & 0xFFFFFFFFu));
            if ((widx & 255) == tid) {
                chosen |= 1ull << (widx >> 8);
                out[(size_t)frow * N_NODES + widx] = __uint_as_float((unsigned)(gb >> 32));
            }
            __syncthreads();
        }
        __syncthreads();
    }
    __syncthreads();
    if (tid == 0) g_nfail = 0;   // reset for next replay
}

// ---------------- launch ----------------
extern "C" void kernel_launch(void* const* d_in, const int* in_sizes, int n_in,
                              void* d_out, int out_size) {
    const int*   idx  = (const int*)  d_in[0];
    const float* emb1 = (const float*)d_in[1];
    const float* emb2 = (const float*)d_in[2];
    const float* W1   = (const float*)d_in[3];
    const float* b1   = (const float*)d_in[4];
    const float* W2   = (const float*)d_in[5];
    const float* b2   = (const float*)d_in[6];
    float* out = (float*)d_out;

    (void)in_sizes; (void)n_in; (void)out_size;

    prep_kernel<<<PGRID, 256>>>(idx, emb1, emb2, W1, b1, W2, b2);

    // mega with Programmatic Stream Serialization: launches while prep runs,
    // self-gates with cudaGridDependencySynchronize() before reading g_P/g_Q.
    {
        cudaLaunchConfig_t cfg = {};
        cfg.gridDim  = dim3(NGROUPS, 1, 1);
        cfg.blockDim = dim3(RPB * 32, 1, 1);
        cudaLaunchAttribute attrs[1];
        attrs[0].id = cudaLaunchAttributeProgrammaticStreamSerialization;
        attrs[0].val.programmaticStreamSerializationAllowed = 1;
        cfg.attrs = attrs;
        cfg.numAttrs = 1;
        cfg.stream = 0;
        cudaLaunchKernelEx(&cfg, mega_kernel, (float*)out);
    }

    fallback_kernel<<<1, 256>>>(out);
}